// round 9
// baseline (speedup 1.0000x reference)
#include <cuda_runtime.h>
#include <cuda_bf16.h>
#include <math.h>

// Shapes fixed by the problem
#define NN     1024
#define LL     30
#define LP     32      // padded latent (2 zero lanes)
#define GG     10000
#define NBATCH 64
#define NT     256     // threads per block
#define GT     512     // genes per block (2 per thread)
#define CH     32      // cells per chunk staged in shared

typedef unsigned long long u64;

// ---- packed f32x2 helpers (sm_103a) ---------------------------------------
#define FMA2(d, a, b, c) \
    asm("fma.rn.f32x2 %0, %1, %2, %3;" : "=l"(d) : "l"(a), "l"(b), "l"(c))
#define ADD2(d, a, b) \
    asm("add.rn.f32x2 %0, %1, %2;" : "=l"(d) : "l"(a), "l"(b))
#define PACK2(d, lo, hi) \
    asm("mov.b64 %0, {%1, %2};" : "=l"(d) : "f"(lo), "f"(hi))
#define UNPACK2(lo, hi, s) \
    asm("mov.b64 {%0, %1}, %2;" : "=f"(lo), "=f"(hi) : "l"(s))

__device__ __forceinline__ float softplus_fast(float x) {
    return fmaxf(x, 0.f) + __logf(1.f + __expf(-fabsf(x)));
}

// ---------------------------------------------------------------------------
// Single fused kernel. Grid = (ceil(G/512), NB), 256 threads x 2 genes.
// Block (gx, b):
//   - builds the cell list of batch b in shared (bc is 4KB, L2-resident)
//   - loads A rows for BOTH genes directly into packed registers (LDG.64),
//     folds W (coalesced, L2-resident) via add.rn.f32x2
//   - streams cells through a padded shared z buffer: per cell 8 LDS.128,
//     each feeding 4 FMA2 across 4 independent chains (2 genes x 2 accs)
//     -> LDS instructions per (cell,gene) halved vs 1-gene version
//   - b==0 plane emits the exp(px_r) tail
// ---------------------------------------------------------------------------
__global__ __launch_bounds__(NT, 2)
void decoder_kernel(const float* __restrict__ z,
                    const int*   __restrict__ bc,
                    const float* __restrict__ sf,
                    const float* __restrict__ W,
                    const float* __restrict__ A,
                    const float* __restrict__ bemb,
                    const float* __restrict__ px_r,
                    float* __restrict__ out) {
    __shared__ __align__(16) float zsh[CH * LP];   // 4096 B
    __shared__ float sfsh[CH];
    __shared__ int   lsh[NN];                      // cell ids of this batch
    __shared__ int   cnt;

    const int tid = threadIdx.x;
    const int g0  = blockIdx.x * GT;
    const int b   = blockIdx.y;
    const int gt  = min(GT, GG - g0);

    const int gA = g0 + tid;
    const int gB = gA + NT;
    const bool actA = (tid < gt);
    const bool actB = (tid + NT < gt);

    if (tid == 0) cnt = 0;

    // exp(px_r) tail, b==0 plane
    if (b == 0) {
        if (actA) out[(size_t)NN * GG + gA] = __expf(px_r[gA]);
        if (actB) out[(size_t)NN * GG + gB] = __expf(px_r[gB]);
    }

    __syncthreads();

    // Build this batch's cell list (order irrelevant: each cell owns its row)
    for (int i = tid; i < NN; i += NT) {
        if (bc[i] == b) { int p = atomicAdd(&cnt, 1); lsh[p] = i; }
    }

    // Fold C[l] = A[b,g,l] + W[l,g] for both genes into packed f32x2 regs.
    u64 C2a[LP / 2], C2b[LP / 2];
    float bbA = 0.f, bbB = 0.f;
    {
        const u64* ArowA = (const u64*)(A + ((size_t)b * GG + gA) * LL);
        const u64* ArowB = (const u64*)(A + ((size_t)b * GG + gB) * LL);
        if (actA) {
#pragma unroll
            for (int q = 0; q < 15; q++) {
                u64 a2 = ArowA[q];
                u64 w2;
                PACK2(w2, W[(2 * q) * GG + gA], W[(2 * q + 1) * GG + gA]);
                ADD2(C2a[q], a2, w2);
            }
            bbA = bemb[(size_t)b * GG + gA];
        } else {
#pragma unroll
            for (int q = 0; q < 15; q++) C2a[q] = 0ULL;
        }
        C2a[15] = 0ULL;
        if (actB) {
#pragma unroll
            for (int q = 0; q < 15; q++) {
                u64 a2 = ArowB[q];
                u64 w2;
                PACK2(w2, W[(2 * q) * GG + gB], W[(2 * q + 1) * GG + gB]);
                ADD2(C2b[q], a2, w2);
            }
            bbB = bemb[(size_t)b * GG + gB];
        } else {
#pragma unroll
            for (int q = 0; q < 15; q++) C2b[q] = 0ULL;
        }
        C2b[15] = 0ULL;
    }

    __syncthreads();
    const int e = cnt;

    for (int c0 = 0; c0 < e; c0 += CH) {
        const int nch = min(CH, e - c0);
        __syncthreads();   // zsh reuse safety
        // stage z rows, padded stride LP=32, pad lanes zeroed
        for (int i = tid; i < nch * LP; i += NT) {
            int j = i >> 5, l = i & 31;
            zsh[i] = (l < LL) ? z[lsh[c0 + j] * LL + l] : 0.f;
        }
        if (tid < nch) sfsh[tid] = sf[lsh[c0 + tid]];
        __syncthreads();

        for (int j = 0; j < nch; j++) {
            const ulonglong2* zp = (const ulonglong2*)(zsh + j * LP);
            u64 aA0 = 0ULL, aA1 = 0ULL, aB0 = 0ULL, aB1 = 0ULL;
#pragma unroll
            for (int q = 0; q < 8; q++) {
                // one LDS.128 -> 4 FMA2 on 4 independent chains,
                // only 4 live z regs at a time
                ulonglong2 v = zp[q];
                FMA2(aA0, C2a[2 * q],     v.x, aA0);
                FMA2(aA1, C2a[2 * q + 1], v.y, aA1);
                FMA2(aB0, C2b[2 * q],     v.x, aB0);
                FMA2(aB1, C2b[2 * q + 1], v.y, aB1);
            }
            const float sfj = sfsh[j];
            const size_t rowbase = (size_t)lsh[c0 + j] * GG;
            if (actA) {
                float x0, x1, y0, y1;
                UNPACK2(x0, x1, aA0);
                UNPACK2(y0, y1, aA1);
                float acc = ((x0 + x1) + (y0 + y1)) + bbA;
                out[rowbase + gA] = softplus_fast(acc) * sfj;
            }
            if (actB) {
                float x0, x1, y0, y1;
                UNPACK2(x0, x1, aB0);
                UNPACK2(y0, y1, aB1);
                float acc = ((x0 + x1) + (y0 + y1)) + bbB;
                out[rowbase + gB] = softplus_fast(acc) * sfj;
            }
        }
    }
}

// ---------------------------------------------------------------------------
// Launch. Inputs per metadata order:
//   0: z [N,L] f32        1: batch_covariate [N] i32   2: size_factor [N,1] f32
//   3: W_amat [L,G] f32   4: A_emb [NB,G,L] f32        5: b_emb [NB,G] f32
//   6: px_r [G] f32
// Output: mean [N,G] f32 followed by inverse_dispersion [G] f32.
// ---------------------------------------------------------------------------
extern "C" void kernel_launch(void* const* d_in, const int* in_sizes, int n_in,
                              void* d_out, int out_size) {
    const float* z    = (const float*)d_in[0];
    const int*   bc   = (const int*)  d_in[1];
    const float* sf   = (const float*)d_in[2];
    const float* W    = (const float*)d_in[3];
    const float* A    = (const float*)d_in[4];
    const float* bemb = (const float*)d_in[5];
    const float* pxr  = (const float*)d_in[6];
    float* out = (float*)d_out;

    dim3 grid((GG + GT - 1) / GT, NBATCH);
    decoder_kernel<<<grid, NT>>>(z, bc, sf, W, A, bemb, pxr, out);
}

// round 10
// speedup vs baseline: 1.0258x; 1.0258x over previous
#include <cuda_runtime.h>
#include <cuda_bf16.h>
#include <math.h>

// Shapes fixed by the problem
#define NN     1024
#define LL     30
#define LP     32      // padded z stride in shared (alignment only; pads never read)
#define GG     10000
#define NBATCH 64
#define NT     256     // threads per block
#define GT     512     // genes per block (2 per thread)
#define CH     32      // cells per chunk staged in shared

typedef unsigned long long u64;

// ---- packed f32x2 helpers (sm_103a) ---------------------------------------
#define FMA2(d, a, b, c) \
    asm("fma.rn.f32x2 %0, %1, %2, %3;" : "=l"(d) : "l"(a), "l"(b), "l"(c))
#define ADD2(d, a, b) \
    asm("add.rn.f32x2 %0, %1, %2;" : "=l"(d) : "l"(a), "l"(b))
#define PACK2(d, lo, hi) \
    asm("mov.b64 %0, {%1, %2};" : "=l"(d) : "f"(lo), "f"(hi))
#define UNPACK2(lo, hi, s) \
    asm("mov.b64 {%0, %1}, %2;" : "=f"(lo), "=f"(hi) : "l"(s))

__device__ __forceinline__ float softplus_fast(float x) {
    return fmaxf(x, 0.f) + __logf(1.f + __expf(-fabsf(x)));
}

// ---------------------------------------------------------------------------
// Single fused kernel. Grid = (ceil(G/512), NB), 256 threads x 2 genes.
// Per (cell, thread): 7 LDS.128 + 1 LDS.64 feed 60 FMA2 over 4 independent
// accumulator chains (2 genes x 2). Loads are issued in two batched phases so
// ptxas can hoist phase-B loads into phase-A's FMA shadow (load-use latency
// amortized once per cell instead of per load).
// ---------------------------------------------------------------------------
__global__ __launch_bounds__(NT, 2)
void decoder_kernel(const float* __restrict__ z,
                    const int*   __restrict__ bc,
                    const float* __restrict__ sf,
                    const float* __restrict__ W,
                    const float* __restrict__ A,
                    const float* __restrict__ bemb,
                    const float* __restrict__ px_r,
                    float* __restrict__ out) {
    __shared__ __align__(16) float zsh[CH * LP];   // 4096 B
    __shared__ float sfsh[CH];
    __shared__ int   lsh[NN];                      // cell ids of this batch
    __shared__ int   cnt;

    const int tid = threadIdx.x;
    const int g0  = blockIdx.x * GT;
    const int b   = blockIdx.y;
    const int gt  = min(GT, GG - g0);

    const int gA = g0 + tid;
    const int gB = gA + NT;
    const bool actA = (tid < gt);
    const bool actB = (tid + NT < gt);

    if (tid == 0) cnt = 0;

    // exp(px_r) tail, b==0 plane
    if (b == 0) {
        if (actA) out[(size_t)NN * GG + gA] = __expf(px_r[gA]);
        if (actB) out[(size_t)NN * GG + gB] = __expf(px_r[gB]);
    }

    __syncthreads();

    // Build this batch's cell list (order irrelevant: each cell owns its row)
    for (int i = tid; i < NN; i += NT) {
        if (bc[i] == b) { int p = atomicAdd(&cnt, 1); lsh[p] = i; }
    }

    // Fold C[l] = A[b,g,l] + W[l,g] for both genes into 15 packed f32x2 regs
    // each. A row = 120B, 8B-aligned -> LDG.64 straight to u64. W coalesced.
    u64 C2a[15], C2b[15];
    float bbA = 0.f, bbB = 0.f;
    {
        const u64* ArowA = (const u64*)(A + ((size_t)b * GG + gA) * LL);
        const u64* ArowB = (const u64*)(A + ((size_t)b * GG + gB) * LL);
        if (actA) {
#pragma unroll
            for (int q = 0; q < 15; q++) {
                u64 w2;
                PACK2(w2, W[(2 * q) * GG + gA], W[(2 * q + 1) * GG + gA]);
                ADD2(C2a[q], ArowA[q], w2);
            }
            bbA = bemb[(size_t)b * GG + gA];
        } else {
#pragma unroll
            for (int q = 0; q < 15; q++) C2a[q] = 0ULL;
        }
        if (actB) {
#pragma unroll
            for (int q = 0; q < 15; q++) {
                u64 w2;
                PACK2(w2, W[(2 * q) * GG + gB], W[(2 * q + 1) * GG + gB]);
                ADD2(C2b[q], ArowB[q], w2);
            }
            bbB = bemb[(size_t)b * GG + gB];
        } else {
#pragma unroll
            for (int q = 0; q < 15; q++) C2b[q] = 0ULL;
        }
    }

    __syncthreads();
    const int e = cnt;

    for (int c0 = 0; c0 < e; c0 += CH) {
        const int nch = min(CH, e - c0);
        __syncthreads();   // zsh reuse safety
        // stage z rows, padded stride LP=32 (pad lanes never read; left as-is)
        for (int i = tid; i < nch * LP; i += NT) {
            int j = i >> 5, l = i & 31;
            if (l < LL) zsh[i] = z[lsh[c0 + j] * LL + l];
        }
        if (tid < nch) sfsh[tid] = sf[lsh[c0 + tid]];
        __syncthreads();

        for (int j = 0; j < nch; j++) {
            const ulonglong2* zp = (const ulonglong2*)(zsh + j * LP);
            const u64* zq       = (const u64*)(zsh + j * LP);
            u64 aA0 = 0ULL, aA1 = 0ULL, aB0 = 0ULL, aB1 = 0ULL;

            // Phase A: 4 batched LDS.128 (pairs 0..7), 16 FMA2
            ulonglong2 v0 = zp[0], v1 = zp[1], v2 = zp[2], v3 = zp[3];
            // Phase B loads issued here so they overlap phase-A FMAs
            ulonglong2 v4 = zp[4], v5 = zp[5], v6 = zp[6];
            u64 vt = zq[14];

            FMA2(aA0, C2a[0], v0.x, aA0);  FMA2(aA1, C2a[1], v0.y, aA1);
            FMA2(aB0, C2b[0], v0.x, aB0);  FMA2(aB1, C2b[1], v0.y, aB1);
            FMA2(aA0, C2a[2], v1.x, aA0);  FMA2(aA1, C2a[3], v1.y, aA1);
            FMA2(aB0, C2b[2], v1.x, aB0);  FMA2(aB1, C2b[3], v1.y, aB1);
            FMA2(aA0, C2a[4], v2.x, aA0);  FMA2(aA1, C2a[5], v2.y, aA1);
            FMA2(aB0, C2b[4], v2.x, aB0);  FMA2(aB1, C2b[5], v2.y, aB1);
            FMA2(aA0, C2a[6], v3.x, aA0);  FMA2(aA1, C2a[7], v3.y, aA1);
            FMA2(aB0, C2b[6], v3.x, aB0);  FMA2(aB1, C2b[7], v3.y, aB1);

            FMA2(aA0, C2a[8],  v4.x, aA0); FMA2(aA1, C2a[9],  v4.y, aA1);
            FMA2(aB0, C2b[8],  v4.x, aB0); FMA2(aB1, C2b[9],  v4.y, aB1);
            FMA2(aA0, C2a[10], v5.x, aA0); FMA2(aA1, C2a[11], v5.y, aA1);
            FMA2(aB0, C2b[10], v5.x, aB0); FMA2(aB1, C2b[11], v5.y, aB1);
            FMA2(aA0, C2a[12], v6.x, aA0); FMA2(aA1, C2a[13], v6.y, aA1);
            FMA2(aB0, C2b[12], v6.x, aB0); FMA2(aB1, C2b[13], v6.y, aB1);
            FMA2(aA0, C2a[14], vt,   aA0);
            FMA2(aB0, C2b[14], vt,   aB0);

            const float sfj = sfsh[j];
            const size_t rowbase = (size_t)lsh[c0 + j] * GG;
            if (actA) {
                float x0, x1, y0, y1;
                UNPACK2(x0, x1, aA0);
                UNPACK2(y0, y1, aA1);
                float acc = ((x0 + x1) + (y0 + y1)) + bbA;
                out[rowbase + gA] = softplus_fast(acc) * sfj;
            }
            if (actB) {
                float x0, x1, y0, y1;
                UNPACK2(x0, x1, aB0);
                UNPACK2(y0, y1, aB1);
                float acc = ((x0 + x1) + (y0 + y1)) + bbB;
                out[rowbase + gB] = softplus_fast(acc) * sfj;
            }
        }
    }
}

// ---------------------------------------------------------------------------
// Launch. Inputs per metadata order:
//   0: z [N,L] f32        1: batch_covariate [N] i32   2: size_factor [N,1] f32
//   3: W_amat [L,G] f32   4: A_emb [NB,G,L] f32        5: b_emb [NB,G] f32
//   6: px_r [G] f32
// Output: mean [N,G] f32 followed by inverse_dispersion [G] f32.
// ---------------------------------------------------------------------------
extern "C" void kernel_launch(void* const* d_in, const int* in_sizes, int n_in,
                              void* d_out, int out_size) {
    const float* z    = (const float*)d_in[0];
    const int*   bc   = (const int*)  d_in[1];
    const float* sf   = (const float*)d_in[2];
    const float* W    = (const float*)d_in[3];
    const float* A    = (const float*)d_in[4];
    const float* bemb = (const float*)d_in[5];
    const float* pxr  = (const float*)d_in[6];
    float* out = (float*)d_out;

    dim3 grid((GG + GT - 1) / GT, NBATCH);
    decoder_kernel<<<grid, NT>>>(z, bc, sf, W, A, bemb, pxr, out);
}